// round 12
// baseline (speedup 1.0000x reference)
#include <cuda_runtime.h>
#include <cuda_bf16.h>
#include <cuda_fp16.h>
#include <math_constants.h>
#include <cstdint>

// Problem constants
#define DD 256
#define TT 4096
#define BBATCH 16
#define KK 1024
#define NTOK (BBATCH * TT)                  // 65536 tokens
#define NDATA ((size_t)BBATCH * DD * TT)    // 16777216 output data elements

// Scratch (no cudaMalloc allowed)
__device__ float          g_e2[KK];
__device__ float          g_r2[NTOK];
__device__ int            g_idx[NTOK];
__device__ double         g_loss_sum;
__device__ float          g_zt[NDATA];          // z transposed [token][d] fp32
__device__ __nv_bfloat16  g_zbf[NDATA];         // z transposed bf16
__device__ __nv_bfloat16  g_ebf[KK * DD];       // emb bf16
__device__ __half         g_dah[(size_t)NTOK * KK];  // approx dists fp16 (128 MB)

__device__ __forceinline__ uint32_t s2u(const void* p) {
    uint32_t a;
    asm("{ .reg .u64 t; cvta.to.shared.u64 t, %1; cvt.u32.u64 %0, t; }"
        : "=r"(a) : "l"(p));
    return a;
}

#define LDSM_X4(r0, r1, r2, r3, addr)                                          \
    asm volatile("ldmatrix.sync.aligned.m8n8.x4.shared.b16 {%0,%1,%2,%3}, [%4];" \
                 : "=r"(r0), "=r"(r1), "=r"(r2), "=r"(r3) : "r"(addr))

#define MMA16816(d, a0, a1, a2, a3, b0, b1)                                    \
    asm volatile("mma.sync.aligned.m16n8k16.row.col.f32.bf16.bf16.f32 "        \
                 "{%0,%1,%2,%3}, {%4,%5,%6,%7}, {%8,%9}, {%0,%1,%2,%3};"       \
                 : "+f"((d)[0]), "+f"((d)[1]), "+f"((d)[2]), "+f"((d)[3])      \
                 : "r"(a0), "r"(a1), "r"(a2), "r"(a3), "r"(b0), "r"(b1))

#define CP_ASYNC16(dst, src)                                                   \
    asm volatile("cp.async.cg.shared.global [%0], [%1], 16;"                   \
                 :: "r"(dst), "l"(src))
#define CP_COMMIT() asm volatile("cp.async.commit_group;" ::: "memory")
#define CP_WAIT0()  asm volatile("cp.async.wait_group 0;" ::: "memory")

// ===========================================================================
// Kernel 0: exact ||e_k||^2 (sequential mul-then-add) + ebf convert + zero loss
// ===========================================================================
__global__ void vq_prep_kernel(const float* __restrict__ emb) {
    int k = blockIdx.x * blockDim.x + threadIdx.x;
    if (k == 0) g_loss_sum = 0.0;
    if (k < KK) {
        const float* e = emb + (size_t)k * DD;
        float acc = 0.0f;
        #pragma unroll 8
        for (int d = 0; d < DD; ++d) {
            float v = e[d];
            acc = __fadd_rn(acc, __fmul_rn(v, v));
            g_ebf[(size_t)k * DD + d] = __float2bfloat16_rn(v);
        }
        g_e2[k] = acc;
    }
}

// ===========================================================================
// Kernel 1: transpose z [b,d,t] -> zt[token][d] fp32 + zbf bf16.
// EXACT R7 version (32x32 tiles, 4KB smem) -- part of R7's fast baseline.
// ===========================================================================
__global__ void vq_convert_kernel(const float* __restrict__ z) {
    __shared__ float tile[32][33];
    const int b = blockIdx.z, d0 = blockIdx.y << 5, t0 = blockIdx.x << 5;
    const int tx = threadIdx.x, ty = threadIdx.y;   // 32 x 8
    const float* src = z + ((size_t)(b << 8) + d0) * TT + t0;
    #pragma unroll
    for (int k = 0; k < 4; ++k)
        tile[ty + k * 8][tx] = src[(size_t)(ty + k * 8) * TT + tx];
    __syncthreads();
    const size_t tokbase = ((size_t)b << 12) + t0;
    #pragma unroll
    for (int k = 0; k < 4; ++k) {
        int tr = ty + k * 8;
        float v = tile[tx][tr];
        size_t o = (tokbase + tr) * DD + d0 + tx;
        g_zt[o]  = v;
        g_zbf[o] = __float2bfloat16_rn(v);
    }
}

// ===========================================================================
// Kernel 2: exact r2 per token. EXACT R7 version (sequential ascending-d,
// bit-matching arithmetic validated R2; uniform-shift argument).
// ===========================================================================
__global__ void vq_r2_kernel() {
    int t = blockIdx.x * blockDim.x + threadIdx.x;
    const float* zr = g_zt + (size_t)t * DD;
    float acc = 0.0f;
    #pragma unroll 8
    for (int d = 0; d < DD; ++d) {
        float v = zr[d];
        acc = __fadd_rn(acc, __fmul_rn(v, v));
    }
    g_r2[t] = acc;
}

// ===========================================================================
// Kernel 3: bf16 HMMA approx-dist GEMM -- R7 structure (227us, 122 regs,
// validated), fp16 epilogue (halves the write traffic that bounded R7).
// 512 threads / 16 warps; warp w: rows rg=w&7, col half ch=w>>3.
// cp.async double-buffered B.
// ===========================================================================
#define ES2_OFF 0                      // 4096 B
#define A_OFF   4096                   // 65536 B
#define B0_OFF  69632                  // 65536 B
#define B1_OFF  135168                 // 65536 B
#define SMEM_TOT 200704

__global__ void __launch_bounds__(512, 1) vq_mma_kernel() {
    extern __shared__ char smem[];
    const uint32_t sb = s2u(smem);
    const int tid = threadIdx.x, wid = tid >> 5, lane = tid & 31;
    const int tok0 = blockIdx.x << 7;
    float* es2s = (float*)(smem + ES2_OFF);

    es2s[tid]       = g_e2[tid];
    es2s[tid + 512] = g_e2[tid + 512];

    const uint4* zsrc = (const uint4*)(g_zbf + ((size_t)tok0 << 8));
    #pragma unroll 2
    for (int i = tid; i < 4096; i += 512) {
        int row = i >> 5, kb = i & 31;
        CP_ASYNC16(sb + A_OFF + row * 512 + ((kb ^ (row & 7)) << 4), zsrc + i);
    }
    {
        const uint4* esrc = (const uint4*)g_ebf;
        #pragma unroll 2
        for (int i = tid; i < 4096; i += 512) {
            int row = i >> 5, kb = i & 31;
            CP_ASYNC16(sb + B0_OFF + row * 512 + ((kb ^ (row & 7)) << 4), esrc + i);
        }
    }
    CP_COMMIT();
    CP_WAIT0();
    __syncthreads();

    // Warp tile mapping (validated R6/R7).
    const int rg = wid & 7, ch = wid >> 3;
    const int m0 = rg << 4, nb0 = ch << 6;
    const int lr = lane & 7;
    const int arow = m0 + lr + (((lane >> 3) & 1) << 3);
    const int akc  = lane >> 4;
    const int brow_off = lr + ((lane >> 4) << 3);
    const int bkc  = (lane >> 3) & 1;
    const uint32_t aBase = sb + A_OFF + (uint32_t)arow * 512;

    for (int c = 0; c < 8; ++c) {
        const int nc0 = c << 7;
        const uint32_t bOff = (c & 1) ? B1_OFF : B0_OFF;

        if (c < 7) {
            const uint32_t nOff = (c & 1) ? B0_OFF : B1_OFF;
            const uint4* esrc = (const uint4*)(g_ebf + ((size_t)(nc0 + 128) << 8));
            #pragma unroll 2
            for (int i = tid; i < 4096; i += 512) {
                int row = i >> 5, kb = i & 31;
                CP_ASYNC16(sb + nOff + row * 512 + ((kb ^ (row & 7)) << 4), esrc + i);
            }
            CP_COMMIT();
        }

        float acc[8][4];
        #pragma unroll
        for (int nt = 0; nt < 8; ++nt)
            #pragma unroll
            for (int q = 0; q < 4; ++q) acc[nt][q] = 0.0f;

        #pragma unroll
        for (int s = 0; s < 16; ++s) {
            uint32_t a0, a1, a2, a3;
            int ach = 2 * s + akc;
            LDSM_X4(a0, a1, a2, a3, aBase + (uint32_t)((ach ^ (arow & 7)) << 4));
            #pragma unroll
            for (int p = 0; p < 4; ++p) {
                int brow = nb0 + (p << 4) + brow_off;
                int bch  = 2 * s + bkc;
                uint32_t b0, b1, b2, b3;
                LDSM_X4(b0, b1, b2, b3,
                        sb + bOff + (uint32_t)brow * 512
                                  + (uint32_t)((bch ^ (brow & 7)) << 4));
                MMA16816(acc[2 * p],     a0, a1, a2, a3, b0, b1);
                MMA16816(acc[2 * p + 1], a0, a1, a2, a3, b2, b3);
            }
        }

        // Epilogue: da = fl(e2 - 2*score) -> fp16, __half2 stores.
        // fp16 quantization absorbed by the select margin (validated R9/R10).
        {
            int r0 = tok0 + m0 + (lane >> 2);
            int cb = (lane & 3) << 1;
            #pragma unroll
            for (int nt = 0; nt < 8; ++nt) {
                int col = nb0 + (nt << 3) + cb;       // 0..127, even
                float e20 = es2s[nc0 + col];
                float e21 = es2s[nc0 + col + 1];
                __half2 v0 = __floats2half2_rn(fmaf(-2.0f, acc[nt][0], e20),
                                               fmaf(-2.0f, acc[nt][1], e21));
                __half2 v1 = __floats2half2_rn(fmaf(-2.0f, acc[nt][2], e20),
                                               fmaf(-2.0f, acc[nt][3], e21));
                *(__half2*)&g_dah[(size_t)r0 * KK + nc0 + col]       = v0;
                *(__half2*)&g_dah[(size_t)(r0 + 8) * KK + nc0 + col] = v1;
            }
        }

        if (c < 7) {
            CP_WAIT0();
            __syncthreads();
        }
    }
}

// ===========================================================================
// Kernel 4: warp-per-token select + exact rescore (validated R7/R9/R10;
// measured 5.5us in R10 thanks to L2-resident g_dah).
// ===========================================================================
__global__ void __launch_bounds__(256) vq_select_kernel(const float* __restrict__ emb) {
    const int warp = threadIdx.x >> 5, lane = threadIdx.x & 31;
    const int tok = (blockIdx.x << 3) + warp;
    const __half* da = g_dah + (size_t)tok * KK;

    float4 v[8];
    float mn = CUDART_INF_F;
    #pragma unroll
    for (int i = 0; i < 8; ++i) {
        uint2 h = *(const uint2*)(da + (i << 7) + (lane << 2));
        float2 f01 = __half22float2(((const __half2*)&h)[0]);
        float2 f23 = __half22float2(((const __half2*)&h)[1]);
        v[i] = make_float4(f01.x, f01.y, f23.x, f23.y);
        mn = fminf(mn, fminf(fminf(v[i].x, v[i].y), fminf(v[i].z, v[i].w)));
    }
    #pragma unroll
    for (int off = 16; off > 0; off >>= 1)
        mn = fminf(mn, __shfl_xor_sync(0xffffffffu, mn, off));

    const float r2 = g_r2[tok];
    // margin = 2B + 2*fp16_quant; B = 2^-6*1.01*||z||*||e||max + eps.
    const float thr = mn + fmaf(0.0325f * 0.015625f, sqrtf(r2), 7e-4f);

    int cnt = 0;
    #pragma unroll
    for (int i = 0; i < 8; ++i)
        cnt += (v[i].x <= thr) + (v[i].y <= thr) + (v[i].z <= thr) + (v[i].w <= thr);
    int off = cnt;
    #pragma unroll
    for (int d = 1; d < 32; d <<= 1) {
        int t2 = __shfl_up_sync(0xffffffffu, off, d);
        if (lane >= d) off += t2;
    }
    const int total = __shfl_sync(0xffffffffu, off, 31);
    const int excl = off - cnt;

    __shared__ unsigned short clist[8][36];
    const float* zr = g_zt + (size_t)tok * DD;
    int bc = 0;

    if (total <= 32) {
        int k = excl;
        #pragma unroll
        for (int i = 0; i < 8; ++i) {
            int base = (i << 7) + (lane << 2);
            if (v[i].x <= thr) clist[warp][k++] = (unsigned short)(base + 0);
            if (v[i].y <= thr) clist[warp][k++] = (unsigned short)(base + 1);
            if (v[i].z <= thr) clist[warp][k++] = (unsigned short)(base + 2);
            if (v[i].w <= thr) clist[warp][k++] = (unsigned short)(base + 3);
        }
        __syncwarp();
        float bd = CUDART_INF_F;
        bc = 0x7fffffff;
        if (lane < total) {
            int code = clist[warp][lane];
            const float* er = emb + ((size_t)code << 8);
            float acc = 0.0f;
            #pragma unroll 8
            for (int d = 0; d < DD; ++d)
                acc = fmaf(zr[d], __ldg(&er[d]), acc);
            bd = __fsub_rn(__fadd_rn(r2, g_e2[code]), __fmul_rn(2.0f, acc));
            bc = code;
        }
        #pragma unroll
        for (int d = 16; d > 0; d >>= 1) {
            float od = __shfl_xor_sync(0xffffffffu, bd, d);
            int   oc = __shfl_xor_sync(0xffffffffu, bc, d);
            if (od < bd || (od == bd && oc < bc)) { bd = od; bc = oc; }
        }
    } else if (lane == 0) {
        float bd = CUDART_INF_F;
        bc = 0;
        for (int code = 0; code < KK; ++code) {
            const float* er = emb + ((size_t)code << 8);
            float acc = 0.0f;
            #pragma unroll 8
            for (int d = 0; d < DD; ++d)
                acc = fmaf(zr[d], __ldg(&er[d]), acc);
            float dist = __fsub_rn(__fadd_rn(r2, g_e2[code]),
                                   __fmul_rn(2.0f, acc));
            if (dist < bd) { bd = dist; bc = code; }
        }
    }
    if (lane == 0) g_idx[tok] = bc;
}

// ===========================================================================
// Kernel 5: gather + straight-through output + loss partial sums (float4,
// measured 78us in R9). out = fl(z + fl(q - z)); loss fl((q-z)^2) in double.
// ===========================================================================
__global__ void vq_output_kernel(const float* __restrict__ z,
                                 const float* __restrict__ emb,
                                 float* __restrict__ out) {
    double local = 0.0;
    const size_t nvec = NDATA >> 2;
    const size_t stride = (size_t)gridDim.x * blockDim.x;
    for (size_t i = (size_t)blockIdx.x * blockDim.x + threadIdx.x; i < nvec; i += stride) {
        size_t e = i << 2;
        int t  = (int)(e & 4095);
        int d  = (int)((e >> 12) & 255);
        int bb = (int)(e >> 20);
        int4 idx = *(const int4*)&g_idx[(bb << 12) + t];
        float4 zv = *(const float4*)&z[e];
        float q0 = __ldg(&emb[((size_t)idx.x << 8) + d]);
        float q1 = __ldg(&emb[((size_t)idx.y << 8) + d]);
        float q2 = __ldg(&emb[((size_t)idx.z << 8) + d]);
        float q3 = __ldg(&emb[((size_t)idx.w << 8) + d]);
        float d0 = __fsub_rn(q0, zv.x), d1 = __fsub_rn(q1, zv.y);
        float d2 = __fsub_rn(q2, zv.z), d3 = __fsub_rn(q3, zv.w);
        float4 ov = make_float4(__fadd_rn(zv.x, d0), __fadd_rn(zv.y, d1),
                                __fadd_rn(zv.z, d2), __fadd_rn(zv.w, d3));
        *(float4*)&out[e] = ov;
        local += (double)__fmul_rn(d0, d0) + (double)__fmul_rn(d1, d1)
               + (double)__fmul_rn(d2, d2) + (double)__fmul_rn(d3, d3);
    }
    #pragma unroll
    for (int off = 16; off > 0; off >>= 1)
        local += __shfl_down_sync(0xffffffffu, local, off);
    __shared__ double wsum[8];
    int lane = threadIdx.x & 31, wid = threadIdx.x >> 5;
    if (lane == 0) wsum[wid] = local;
    __syncthreads();
    if (threadIdx.x == 0) {
        double s = 0.0;
        #pragma unroll
        for (int i = 0; i < 8; ++i) s += wsum[i];
        atomicAdd(&g_loss_sum, s);
    }
}

// ===========================================================================
// Kernel 6: finalize loss = fl(m + fl(0.25*m)).
// ===========================================================================
__global__ void vq_finalize_kernel(float* __restrict__ out, int out_size) {
    if (threadIdx.x == 0 && blockIdx.x == 0) {
        if ((size_t)out_size > NDATA) {
            float m = (float)(g_loss_sum * (1.0 / 16777216.0));
            out[NDATA] = __fadd_rn(m, __fmul_rn(0.25f, m));
        }
    }
}

// ===========================================================================
extern "C" void kernel_launch(void* const* d_in, const int* in_sizes, int n_in,
                              void* d_out, int out_size) {
    const float* z   = (const float*)d_in[0];
    const float* emb = (const float*)d_in[1];
    if (n_in >= 2 && in_sizes[0] == KK * DD && (size_t)in_sizes[1] == NDATA) {
        const float* tmp = z; z = emb; emb = tmp;
    }
    float* out = (float*)d_out;

    cudaFuncSetAttribute((const void*)vq_mma_kernel,
                         cudaFuncAttributeMaxDynamicSharedMemorySize, SMEM_TOT);

    vq_prep_kernel<<<4, 256>>>(emb);
    vq_convert_kernel<<<dim3(TT / 32, DD / 32, BBATCH), dim3(32, 8)>>>(z);
    vq_r2_kernel<<<NTOK / 256, 256>>>();
    vq_mma_kernel<<<NTOK / 128, 512, SMEM_TOT>>>();
    vq_select_kernel<<<NTOK / 8, 256>>>(emb);
    vq_output_kernel<<<2048, 256>>>(z, emb, out);
    vq_finalize_kernel<<<1, 32>>>(out, out_size);
}

// round 13
// speedup vs baseline: 9.3900x; 9.3900x over previous
#include <cuda_runtime.h>
#include <cuda_bf16.h>
#include <cuda_fp16.h>
#include <math_constants.h>
#include <cstdint>

// Problem constants
#define DD 256
#define TT 4096
#define BBATCH 16
#define KK 1024
#define NTOK (BBATCH * TT)                  // 65536 tokens
#define NDATA ((size_t)BBATCH * DD * TT)    // 16777216 output data elements

// Scratch (no cudaMalloc allowed)
__device__ float          g_e2[KK];
__device__ float          g_r2[NTOK];
__device__ int            g_idx[NTOK];
__device__ double         g_loss_sum;
__device__ float          g_zt[NDATA];          // z transposed [token][d] fp32
__device__ __nv_bfloat16  g_zbf[NDATA];         // z transposed bf16
__device__ __nv_bfloat16  g_ebf[KK * DD];       // emb bf16
__device__ __half         g_dah[(size_t)NTOK * KK];  // approx dists fp16 (128 MB)

__device__ __forceinline__ uint32_t s2u(const void* p) {
    uint32_t a;
    asm("{ .reg .u64 t; cvta.to.shared.u64 t, %1; cvt.u32.u64 %0, t; }"
        : "=r"(a) : "l"(p));
    return a;
}

#define LDSM_X4(r0, r1, r2, r3, addr)                                          \
    asm volatile("ldmatrix.sync.aligned.m8n8.x4.shared.b16 {%0,%1,%2,%3}, [%4];" \
                 : "=r"(r0), "=r"(r1), "=r"(r2), "=r"(r3) : "r"(addr))

#define MMA16816(d, a0, a1, a2, a3, b0, b1)                                    \
    asm volatile("mma.sync.aligned.m16n8k16.row.col.f32.bf16.bf16.f32 "        \
                 "{%0,%1,%2,%3}, {%4,%5,%6,%7}, {%8,%9}, {%0,%1,%2,%3};"       \
                 : "+f"((d)[0]), "+f"((d)[1]), "+f"((d)[2]), "+f"((d)[3])      \
                 : "r"(a0), "r"(a1), "r"(a2), "r"(a3), "r"(b0), "r"(b1))

#define CP_ASYNC16(dst, src)                                                   \
    asm volatile("cp.async.cg.shared.global [%0], [%1], 16;"                   \
                 :: "r"(dst), "l"(src))
#define CP_COMMIT() asm volatile("cp.async.commit_group;" ::: "memory")
#define CP_WAIT0()  asm volatile("cp.async.wait_group 0;" ::: "memory")

// Exact rescore of one code: sequential ascending-d fused fmaf (bit-matches
// the reference; validated R2/R7). float4 loads do NOT change the fma order.
__device__ __forceinline__ float exact_dist(const float* __restrict__ zr,
                                            const float* __restrict__ er,
                                            float r2, float e2) {
    float acc = 0.0f;
    #pragma unroll 8
    for (int d = 0; d < DD; d += 4) {
        float4 z4 = *(const float4*)&zr[d];
        float4 e4 = __ldg((const float4*)&er[d]);
        acc = fmaf(z4.x, e4.x, acc);
        acc = fmaf(z4.y, e4.y, acc);
        acc = fmaf(z4.z, e4.z, acc);
        acc = fmaf(z4.w, e4.w, acc);
    }
    return __fsub_rn(__fadd_rn(r2, e2), __fmul_rn(2.0f, acc));
}

// ===========================================================================
// Kernel 0: exact ||e_k||^2 (sequential mul-then-add) + ebf convert + zero loss
// ===========================================================================
__global__ void vq_prep_kernel(const float* __restrict__ emb) {
    int k = blockIdx.x * blockDim.x + threadIdx.x;
    if (k == 0) g_loss_sum = 0.0;
    if (k < KK) {
        const float* e = emb + (size_t)k * DD;
        float acc = 0.0f;
        #pragma unroll 8
        for (int d = 0; d < DD; ++d) {
            float v = e[d];
            acc = __fadd_rn(acc, __fmul_rn(v, v));
            g_ebf[(size_t)k * DD + d] = __float2bfloat16_rn(v);
        }
        g_e2[k] = acc;
    }
}

// ===========================================================================
// Kernel 1: transpose z [b,d,t] -> zt[token][d] fp32 + zbf bf16 (R7 version).
// ===========================================================================
__global__ void vq_convert_kernel(const float* __restrict__ z) {
    __shared__ float tile[32][33];
    const int b = blockIdx.z, d0 = blockIdx.y << 5, t0 = blockIdx.x << 5;
    const int tx = threadIdx.x, ty = threadIdx.y;   // 32 x 8
    const float* src = z + ((size_t)(b << 8) + d0) * TT + t0;
    #pragma unroll
    for (int k = 0; k < 4; ++k)
        tile[ty + k * 8][tx] = src[(size_t)(ty + k * 8) * TT + tx];
    __syncthreads();
    const size_t tokbase = ((size_t)b << 12) + t0;
    #pragma unroll
    for (int k = 0; k < 4; ++k) {
        int tr = ty + k * 8;
        float v = tile[tx][tr];
        size_t o = (tokbase + tr) * DD + d0 + tx;
        g_zt[o]  = v;
        g_zbf[o] = __float2bfloat16_rn(v);
    }
}

// ===========================================================================
// Kernel 2: exact r2 per token (R7 version; validated R2 arithmetic).
// ===========================================================================
__global__ void vq_r2_kernel() {
    int t = blockIdx.x * blockDim.x + threadIdx.x;
    const float* zr = g_zt + (size_t)t * DD;
    float acc = 0.0f;
    #pragma unroll 8
    for (int d = 0; d < DD; ++d) {
        float v = zr[d];
        acc = __fadd_rn(acc, __fmul_rn(v, v));
    }
    g_r2[t] = acc;
}

// ===========================================================================
// Kernel 3: bf16 HMMA approx-dist GEMM -- R7 structure, fp16 epilogue
// (measured 147us in R12). cp.async double-buffered B.
// ===========================================================================
#define ES2_OFF 0                      // 4096 B
#define A_OFF   4096                   // 65536 B
#define B0_OFF  69632                  // 65536 B
#define B1_OFF  135168                 // 65536 B
#define SMEM_TOT 200704

__global__ void __launch_bounds__(512, 1) vq_mma_kernel() {
    extern __shared__ char smem[];
    const uint32_t sb = s2u(smem);
    const int tid = threadIdx.x, wid = tid >> 5, lane = tid & 31;
    const int tok0 = blockIdx.x << 7;
    float* es2s = (float*)(smem + ES2_OFF);

    es2s[tid]       = g_e2[tid];
    es2s[tid + 512] = g_e2[tid + 512];

    const uint4* zsrc = (const uint4*)(g_zbf + ((size_t)tok0 << 8));
    #pragma unroll 2
    for (int i = tid; i < 4096; i += 512) {
        int row = i >> 5, kb = i & 31;
        CP_ASYNC16(sb + A_OFF + row * 512 + ((kb ^ (row & 7)) << 4), zsrc + i);
    }
    {
        const uint4* esrc = (const uint4*)g_ebf;
        #pragma unroll 2
        for (int i = tid; i < 4096; i += 512) {
            int row = i >> 5, kb = i & 31;
            CP_ASYNC16(sb + B0_OFF + row * 512 + ((kb ^ (row & 7)) << 4), esrc + i);
        }
    }
    CP_COMMIT();
    CP_WAIT0();
    __syncthreads();

    const int rg = wid & 7, ch = wid >> 3;
    const int m0 = rg << 4, nb0 = ch << 6;
    const int lr = lane & 7;
    const int arow = m0 + lr + (((lane >> 3) & 1) << 3);
    const int akc  = lane >> 4;
    const int brow_off = lr + ((lane >> 4) << 3);
    const int bkc  = (lane >> 3) & 1;
    const uint32_t aBase = sb + A_OFF + (uint32_t)arow * 512;

    for (int c = 0; c < 8; ++c) {
        const int nc0 = c << 7;
        const uint32_t bOff = (c & 1) ? B1_OFF : B0_OFF;

        if (c < 7) {
            const uint32_t nOff = (c & 1) ? B0_OFF : B1_OFF;
            const uint4* esrc = (const uint4*)(g_ebf + ((size_t)(nc0 + 128) << 8));
            #pragma unroll 2
            for (int i = tid; i < 4096; i += 512) {
                int row = i >> 5, kb = i & 31;
                CP_ASYNC16(sb + nOff + row * 512 + ((kb ^ (row & 7)) << 4), esrc + i);
            }
            CP_COMMIT();
        }

        float acc[8][4];
        #pragma unroll
        for (int nt = 0; nt < 8; ++nt)
            #pragma unroll
            for (int q = 0; q < 4; ++q) acc[nt][q] = 0.0f;

        #pragma unroll
        for (int s = 0; s < 16; ++s) {
            uint32_t a0, a1, a2, a3;
            int ach = 2 * s + akc;
            LDSM_X4(a0, a1, a2, a3, aBase + (uint32_t)((ach ^ (arow & 7)) << 4));
            #pragma unroll
            for (int p = 0; p < 4; ++p) {
                int brow = nb0 + (p << 4) + brow_off;
                int bch  = 2 * s + bkc;
                uint32_t b0, b1, b2, b3;
                LDSM_X4(b0, b1, b2, b3,
                        sb + bOff + (uint32_t)brow * 512
                                  + (uint32_t)((bch ^ (brow & 7)) << 4));
                MMA16816(acc[2 * p],     a0, a1, a2, a3, b0, b1);
                MMA16816(acc[2 * p + 1], a0, a1, a2, a3, b2, b3);
            }
        }

        {
            int r0 = tok0 + m0 + (lane >> 2);
            int cb = (lane & 3) << 1;
            #pragma unroll
            for (int nt = 0; nt < 8; ++nt) {
                int col = nb0 + (nt << 3) + cb;
                float e20 = es2s[nc0 + col];
                float e21 = es2s[nc0 + col + 1];
                __half2 v0 = __floats2half2_rn(fmaf(-2.0f, acc[nt][0], e20),
                                               fmaf(-2.0f, acc[nt][1], e21));
                __half2 v1 = __floats2half2_rn(fmaf(-2.0f, acc[nt][2], e20),
                                               fmaf(-2.0f, acc[nt][3], e21));
                *(__half2*)&g_dah[(size_t)r0 * KK + nc0 + col]       = v0;
                *(__half2*)&g_dah[(size_t)(r0 + 8) * KK + nc0 + col] = v1;
            }
        }

        if (c < 7) {
            CP_WAIT0();
            __syncthreads();
        }
    }
}

// ===========================================================================
// Kernel 4: warp-per-token select + exact rescore.
// CHANGE vs R12 (the indicted 6ms mechanism): the >32-candidate fallback is
// now a WARP-PARALLEL exact full scan (lane l covers codes [32l,32l+32) in
// ascending order) instead of a lane-0 serial scan. Per-code arithmetic is
// the identical sequential fmaf chain; the (dist, lowest-code) reduce gives
// exactly the reference's lowest-index argmin. Rescore loads vectorized
// float4 (same fma order).
// ===========================================================================
__global__ void __launch_bounds__(256) vq_select_kernel(const float* __restrict__ emb) {
    const int warp = threadIdx.x >> 5, lane = threadIdx.x & 31;
    const int tok = (blockIdx.x << 3) + warp;
    const __half* da = g_dah + (size_t)tok * KK;

    float4 v[8];
    float mn = CUDART_INF_F;
    #pragma unroll
    for (int i = 0; i < 8; ++i) {
        uint2 h = *(const uint2*)(da + (i << 7) + (lane << 2));
        float2 f01 = __half22float2(((const __half2*)&h)[0]);
        float2 f23 = __half22float2(((const __half2*)&h)[1]);
        v[i] = make_float4(f01.x, f01.y, f23.x, f23.y);
        mn = fminf(mn, fminf(fminf(v[i].x, v[i].y), fminf(v[i].z, v[i].w)));
    }
    #pragma unroll
    for (int off = 16; off > 0; off >>= 1)
        mn = fminf(mn, __shfl_xor_sync(0xffffffffu, mn, off));

    const float r2 = g_r2[tok];
    // margin = 2B + 2*fp16_quant; B = 2^-6*1.01*||z||*||e||max + eps.
    const float thr = mn + fmaf(0.0325f * 0.015625f, sqrtf(r2), 7e-4f);

    int cnt = 0;
    #pragma unroll
    for (int i = 0; i < 8; ++i)
        cnt += (v[i].x <= thr) + (v[i].y <= thr) + (v[i].z <= thr) + (v[i].w <= thr);
    int off = cnt;
    #pragma unroll
    for (int d = 1; d < 32; d <<= 1) {
        int t2 = __shfl_up_sync(0xffffffffu, off, d);
        if (lane >= d) off += t2;
    }
    const int total = __shfl_sync(0xffffffffu, off, 31);
    const int excl = off - cnt;

    __shared__ unsigned short clist[8][36];
    const float* zr = g_zt + (size_t)tok * DD;

    float bd = CUDART_INF_F;
    int   bc = 0x7fffffff;

    if (total <= 32) {
        int k = excl;
        #pragma unroll
        for (int i = 0; i < 8; ++i) {
            int base = (i << 7) + (lane << 2);
            if (v[i].x <= thr) clist[warp][k++] = (unsigned short)(base + 0);
            if (v[i].y <= thr) clist[warp][k++] = (unsigned short)(base + 1);
            if (v[i].z <= thr) clist[warp][k++] = (unsigned short)(base + 2);
            if (v[i].w <= thr) clist[warp][k++] = (unsigned short)(base + 3);
        }
        __syncwarp();
        if (lane < total) {
            int code = clist[warp][lane];
            bd = exact_dist(zr, emb + ((size_t)code << 8), r2, g_e2[code]);
            bc = code;
        }
    } else {
        // Warp-parallel exact full scan: lane l covers codes 32l..32l+31
        // ascending; strict < keeps lane-local lowest-index min.
        #pragma unroll 1
        for (int s = 0; s < 32; ++s) {
            int code = (lane << 5) + s;
            float dist = exact_dist(zr, emb + ((size_t)code << 8),
                                    r2, g_e2[code]);
            if (dist < bd) { bd = dist; bc = code; }
        }
    }
    // (dist, lowest-code) reduction -- lowest-index tie-break globally.
    #pragma unroll
    for (int d = 16; d > 0; d >>= 1) {
        float od = __shfl_xor_sync(0xffffffffu, bd, d);
        int   oc = __shfl_xor_sync(0xffffffffu, bc, d);
        if (od < bd || (od == bd && oc < bc)) { bd = od; bc = oc; }
    }
    if (lane == 0) g_idx[tok] = bc;
}

// ===========================================================================
// Kernel 5: gather + straight-through output + loss partial sums (float4,
// measured 78us R9). out = fl(z + fl(q - z)); loss fl((q-z)^2) in double.
// ===========================================================================
__global__ void vq_output_kernel(const float* __restrict__ z,
                                 const float* __restrict__ emb,
                                 float* __restrict__ out) {
    double local = 0.0;
    const size_t nvec = NDATA >> 2;
    const size_t stride = (size_t)gridDim.x * blockDim.x;
    for (size_t i = (size_t)blockIdx.x * blockDim.x + threadIdx.x; i < nvec; i += stride) {
        size_t e = i << 2;
        int t  = (int)(e & 4095);
        int d  = (int)((e >> 12) & 255);
        int bb = (int)(e >> 20);
        int4 idx = *(const int4*)&g_idx[(bb << 12) + t];
        float4 zv = *(const float4*)&z[e];
        float q0 = __ldg(&emb[((size_t)idx.x << 8) + d]);
        float q1 = __ldg(&emb[((size_t)idx.y << 8) + d]);
        float q2 = __ldg(&emb[((size_t)idx.z << 8) + d]);
        float q3 = __ldg(&emb[((size_t)idx.w << 8) + d]);
        float d0 = __fsub_rn(q0, zv.x), d1 = __fsub_rn(q1, zv.y);
        float d2 = __fsub_rn(q2, zv.z), d3 = __fsub_rn(q3, zv.w);
        float4 ov = make_float4(__fadd_rn(zv.x, d0), __fadd_rn(zv.y, d1),
                                __fadd_rn(zv.z, d2), __fadd_rn(zv.w, d3));
        *(float4*)&out[e] = ov;
        local += (double)__fmul_rn(d0, d0) + (double)__fmul_rn(d1, d1)
               + (double)__fmul_rn(d2, d2) + (double)__fmul_rn(d3, d3);
    }
    #pragma unroll
    for (int off = 16; off > 0; off >>= 1)
        local += __shfl_down_sync(0xffffffffu, local, off);
    __shared__ double wsum[8];
    int lane = threadIdx.x & 31, wid = threadIdx.x >> 5;
    if (lane == 0) wsum[wid] = local;
    __syncthreads();
    if (threadIdx.x == 0) {
        double s = 0.0;
        #pragma unroll
        for (int i = 0; i < 8; ++i) s += wsum[i];
        atomicAdd(&g_loss_sum, s);
    }
}

// ===========================================================================
// Kernel 6: finalize loss = fl(m + fl(0.25*m)).
// ===========================================================================
__global__ void vq_finalize_kernel(float* __restrict__ out, int out_size) {
    if (threadIdx.x == 0 && blockIdx.x == 0) {
        if ((size_t)out_size > NDATA) {
            float m = (float)(g_loss_sum * (1.0 / 16777216.0));
            out[NDATA] = __fadd_rn(m, __fmul_rn(0.25f, m));
        }
    }
}

// ===========================================================================
extern "C" void kernel_launch(void* const* d_in, const int* in_sizes, int n_in,
                              void* d_out, int out_size) {
    const float* z   = (const float*)d_in[0];
    const float* emb = (const float*)d_in[1];
    if (n_in >= 2 && in_sizes[0] == KK * DD && (size_t)in_sizes[1] == NDATA) {
        const float* tmp = z; z = emb; emb = tmp;
    }
    float* out = (float*)d_out;

    cudaFuncSetAttribute((const void*)vq_mma_kernel,
                         cudaFuncAttributeMaxDynamicSharedMemorySize, SMEM_TOT);

    vq_prep_kernel<<<4, 256>>>(emb);
    vq_convert_kernel<<<dim3(TT / 32, DD / 32, BBATCH), dim3(32, 8)>>>(z);
    vq_r2_kernel<<<NTOK / 256, 256>>>();
    vq_mma_kernel<<<NTOK / 128, 512, SMEM_TOT>>>();
    vq_select_kernel<<<NTOK / 8, 256>>>(emb);
    vq_output_kernel<<<2048, 256>>>(z, emb, out);
    vq_finalize_kernel<<<1, 32>>>(out, out_size);
}

// round 14
// speedup vs baseline: 11.4399x; 1.2183x over previous
#include <cuda_runtime.h>
#include <cuda_fp16.h>
#include <math_constants.h>
#include <cstdint>

// Problem constants
#define DD 256
#define TT 4096
#define BBATCH 16
#define KK 1024
#define NTOK (BBATCH * TT)                  // 65536 tokens
#define NDATA ((size_t)BBATCH * DD * TT)    // 16777216 output data elements

// Scratch (no cudaMalloc allowed)
__device__ float          g_e2[KK];
__device__ float          g_r2[NTOK];
__device__ int            g_idx[NTOK];
__device__ double         g_loss_sum;
__device__ float          g_zt[NDATA];          // z transposed [token][d] fp32
__device__ __half         g_zh[NDATA];          // z transposed fp16
__device__ __half         g_eh[KK * DD];        // emb fp16
__device__ __half         g_dah[(size_t)NTOK * KK];  // approx dists fp16 (128 MB)

__device__ __forceinline__ uint32_t s2u(const void* p) {
    uint32_t a;
    asm("{ .reg .u64 t; cvta.to.shared.u64 t, %1; cvt.u32.u64 %0, t; }"
        : "=r"(a) : "l"(p));
    return a;
}

#define LDSM_X4(r0, r1, r2, r3, addr)                                          \
    asm volatile("ldmatrix.sync.aligned.m8n8.x4.shared.b16 {%0,%1,%2,%3}, [%4];" \
                 : "=r"(r0), "=r"(r1), "=r"(r2), "=r"(r3) : "r"(addr))

// fp16 HMMA: same shape/fragment layout as the bf16 variant (validated), u=2^-11.
#define MMA16816(d, a0, a1, a2, a3, b0, b1)                                    \
    asm volatile("mma.sync.aligned.m16n8k16.row.col.f32.f16.f16.f32 "          \
                 "{%0,%1,%2,%3}, {%4,%5,%6,%7}, {%8,%9}, {%0,%1,%2,%3};"       \
                 : "+f"((d)[0]), "+f"((d)[1]), "+f"((d)[2]), "+f"((d)[3])      \
                 : "r"(a0), "r"(a1), "r"(a2), "r"(a3), "r"(b0), "r"(b1))

#define CP_ASYNC16(dst, src)                                                   \
    asm volatile("cp.async.cg.shared.global [%0], [%1], 16;"                   \
                 :: "r"(dst), "l"(src))
#define CP_COMMIT() asm volatile("cp.async.commit_group;" ::: "memory")
#define CP_WAIT0()  asm volatile("cp.async.wait_group 0;" ::: "memory")

// Exact rescore of one code: sequential ascending-d fused fmaf (bit-matches
// the reference; validated R2/R7/R13). float4 loads keep the fma order.
__device__ __forceinline__ float exact_dist(const float* __restrict__ zr,
                                            const float* __restrict__ er,
                                            float r2, float e2) {
    float acc = 0.0f;
    #pragma unroll 8
    for (int d = 0; d < DD; d += 4) {
        float4 z4 = *(const float4*)&zr[d];
        float4 e4 = __ldg((const float4*)&er[d]);
        acc = fmaf(z4.x, e4.x, acc);
        acc = fmaf(z4.y, e4.y, acc);
        acc = fmaf(z4.z, e4.z, acc);
        acc = fmaf(z4.w, e4.w, acc);
    }
    return __fsub_rn(__fadd_rn(r2, e2), __fmul_rn(2.0f, acc));
}

// ===========================================================================
// Kernel 0: exact ||e_k||^2 (sequential mul-then-add) + fp16 convert + zero loss
// ===========================================================================
__global__ void vq_prep_kernel(const float* __restrict__ emb) {
    int k = blockIdx.x * blockDim.x + threadIdx.x;
    if (k == 0) g_loss_sum = 0.0;
    if (k < KK) {
        const float* e = emb + (size_t)k * DD;
        float acc = 0.0f;
        #pragma unroll 8
        for (int d = 0; d < DD; ++d) {
            float v = e[d];
            acc = __fadd_rn(acc, __fmul_rn(v, v));
            g_eh[(size_t)k * DD + d] = __float2half_rn(v);
        }
        g_e2[k] = acc;
    }
}

// ===========================================================================
// Kernel 1: transpose z [b,d,t] -> zt[token][d] fp32 + zh fp16 (R7 structure).
// ===========================================================================
__global__ void vq_convert_kernel(const float* __restrict__ z) {
    __shared__ float tile[32][33];
    const int b = blockIdx.z, d0 = blockIdx.y << 5, t0 = blockIdx.x << 5;
    const int tx = threadIdx.x, ty = threadIdx.y;   // 32 x 8
    const float* src = z + ((size_t)(b << 8) + d0) * TT + t0;
    #pragma unroll
    for (int k = 0; k < 4; ++k)
        tile[ty + k * 8][tx] = src[(size_t)(ty + k * 8) * TT + tx];
    __syncthreads();
    const size_t tokbase = ((size_t)b << 12) + t0;
    #pragma unroll
    for (int k = 0; k < 4; ++k) {
        int tr = ty + k * 8;
        float v = tile[tx][tr];
        size_t o = (tokbase + tr) * DD + d0 + tx;
        g_zt[o] = v;
        g_zh[o] = __float2half_rn(v);
    }
}

// ===========================================================================
// Kernel 2: exact r2 per token (validated R2 arithmetic).
// ===========================================================================
__global__ void vq_r2_kernel() {
    int t = blockIdx.x * blockDim.x + threadIdx.x;
    const float* zr = g_zt + (size_t)t * DD;
    float acc = 0.0f;
    #pragma unroll 8
    for (int d = 0; d < DD; ++d) {
        float v = zr[d];
        acc = __fadd_rn(acc, __fmul_rn(v, v));
    }
    g_r2[t] = acc;
}

// ===========================================================================
// Kernel 3: fp16 HMMA approx-dist GEMM -- R13 structure (146us measured),
// inputs switched bf16->fp16 (same fragment maps). cp.async double-buffered B.
// ===========================================================================
#define ES2_OFF 0                      // 4096 B
#define A_OFF   4096                   // 65536 B
#define B0_OFF  69632                  // 65536 B
#define B1_OFF  135168                 // 65536 B
#define SMEM_TOT 200704

__global__ void __launch_bounds__(512, 1) vq_mma_kernel() {
    extern __shared__ char smem[];
    const uint32_t sb = s2u(smem);
    const int tid = threadIdx.x, wid = tid >> 5, lane = tid & 31;
    const int tok0 = blockIdx.x << 7;
    float* es2s = (float*)(smem + ES2_OFF);

    es2s[tid]       = g_e2[tid];
    es2s[tid + 512] = g_e2[tid + 512];

    const uint4* zsrc = (const uint4*)(g_zh + ((size_t)tok0 << 8));
    #pragma unroll 2
    for (int i = tid; i < 4096; i += 512) {
        int row = i >> 5, kb = i & 31;
        CP_ASYNC16(sb + A_OFF + row * 512 + ((kb ^ (row & 7)) << 4), zsrc + i);
    }
    {
        const uint4* esrc = (const uint4*)g_eh;
        #pragma unroll 2
        for (int i = tid; i < 4096; i += 512) {
            int row = i >> 5, kb = i & 31;
            CP_ASYNC16(sb + B0_OFF + row * 512 + ((kb ^ (row & 7)) << 4), esrc + i);
        }
    }
    CP_COMMIT();
    CP_WAIT0();
    __syncthreads();

    const int rg = wid & 7, ch = wid >> 3;
    const int m0 = rg << 4, nb0 = ch << 6;
    const int lr = lane & 7;
    const int arow = m0 + lr + (((lane >> 3) & 1) << 3);
    const int akc  = lane >> 4;
    const int brow_off = lr + ((lane >> 4) << 3);
    const int bkc  = (lane >> 3) & 1;
    const uint32_t aBase = sb + A_OFF + (uint32_t)arow * 512;

    for (int c = 0; c < 8; ++c) {
        const int nc0 = c << 7;
        const uint32_t bOff = (c & 1) ? B1_OFF : B0_OFF;

        if (c < 7) {
            const uint32_t nOff = (c & 1) ? B0_OFF : B1_OFF;
            const uint4* esrc = (const uint4*)(g_eh + ((size_t)(nc0 + 128) << 8));
            #pragma unroll 2
            for (int i = tid; i < 4096; i += 512) {
                int row = i >> 5, kb = i & 31;
                CP_ASYNC16(sb + nOff + row * 512 + ((kb ^ (row & 7)) << 4), esrc + i);
            }
            CP_COMMIT();
        }

        float acc[8][4];
        #pragma unroll
        for (int nt = 0; nt < 8; ++nt)
            #pragma unroll
            for (int q = 0; q < 4; ++q) acc[nt][q] = 0.0f;

        #pragma unroll
        for (int s = 0; s < 16; ++s) {
            uint32_t a0, a1, a2, a3;
            int ach = 2 * s + akc;
            LDSM_X4(a0, a1, a2, a3, aBase + (uint32_t)((ach ^ (arow & 7)) << 4));
            #pragma unroll
            for (int p = 0; p < 4; ++p) {
                int brow = nb0 + (p << 4) + brow_off;
                int bch  = 2 * s + bkc;
                uint32_t b0, b1, b2, b3;
                LDSM_X4(b0, b1, b2, b3,
                        sb + bOff + (uint32_t)brow * 512
                                  + (uint32_t)((bch ^ (brow & 7)) << 4));
                MMA16816(acc[2 * p],     a0, a1, a2, a3, b0, b1);
                MMA16816(acc[2 * p + 1], a0, a1, a2, a3, b2, b3);
            }
        }

        {
            int r0 = tok0 + m0 + (lane >> 2);
            int cb = (lane & 3) << 1;
            #pragma unroll
            for (int nt = 0; nt < 8; ++nt) {
                int col = nb0 + (nt << 3) + cb;
                float e20 = es2s[nc0 + col];
                float e21 = es2s[nc0 + col + 1];
                __half2 v0 = __floats2half2_rn(fmaf(-2.0f, acc[nt][0], e20),
                                               fmaf(-2.0f, acc[nt][1], e21));
                __half2 v1 = __floats2half2_rn(fmaf(-2.0f, acc[nt][2], e20),
                                               fmaf(-2.0f, acc[nt][3], e21));
                *(__half2*)&g_dah[(size_t)r0 * KK + nc0 + col]       = v0;
                *(__half2*)&g_dah[(size_t)(r0 + 8) * KK + nc0 + col] = v1;
            }
        }

        if (c < 7) {
            CP_WAIT0();
            __syncthreads();
        }
    }
}

// ===========================================================================
// Kernel 4: warp-per-token select + exact rescore (R13 structure, WIN).
// Margin tightened for fp16 inputs: dist_err <= 2*(2^-10*1.001+1.5e-5)
// * ||z|| * ||e||max = 3.1e-5*||z||; margin = 8e-5*||z|| (29% slack)
// + 6e-4 (fp16-storage 2q for |da|<=0.5 + epilogue ulps + subnormal slop).
// Fallback >32 candidates: warp-parallel exact full scan (validated R13).
// ===========================================================================
__global__ void __launch_bounds__(256) vq_select_kernel(const float* __restrict__ emb) {
    const int warp = threadIdx.x >> 5, lane = threadIdx.x & 31;
    const int tok = (blockIdx.x << 3) + warp;
    const __half* da = g_dah + (size_t)tok * KK;

    float4 v[8];
    float mn = CUDART_INF_F;
    #pragma unroll
    for (int i = 0; i < 8; ++i) {
        uint2 h = *(const uint2*)(da + (i << 7) + (lane << 2));
        float2 f01 = __half22float2(((const __half2*)&h)[0]);
        float2 f23 = __half22float2(((const __half2*)&h)[1]);
        v[i] = make_float4(f01.x, f01.y, f23.x, f23.y);
        mn = fminf(mn, fminf(fminf(v[i].x, v[i].y), fminf(v[i].z, v[i].w)));
    }
    #pragma unroll
    for (int off = 16; off > 0; off >>= 1)
        mn = fminf(mn, __shfl_xor_sync(0xffffffffu, mn, off));

    const float r2 = g_r2[tok];
    const float thr = mn + fmaf(8e-5f, sqrtf(r2), 6e-4f);

    int cnt = 0;
    #pragma unroll
    for (int i = 0; i < 8; ++i)
        cnt += (v[i].x <= thr) + (v[i].y <= thr) + (v[i].z <= thr) + (v[i].w <= thr);
    int off = cnt;
    #pragma unroll
    for (int d = 1; d < 32; d <<= 1) {
        int t2 = __shfl_up_sync(0xffffffffu, off, d);
        if (lane >= d) off += t2;
    }
    const int total = __shfl_sync(0xffffffffu, off, 31);
    const int excl = off - cnt;

    __shared__ unsigned short clist[8][36];
    const float* zr = g_zt + (size_t)tok * DD;

    float bd = CUDART_INF_F;
    int   bc = 0x7fffffff;

    if (total <= 32) {
        int k = excl;
        #pragma unroll
        for (int i = 0; i < 8; ++i) {
            int base = (i << 7) + (lane << 2);
            if (v[i].x <= thr) clist[warp][k++] = (unsigned short)(base + 0);
            if (v[i].y <= thr) clist[warp][k++] = (unsigned short)(base + 1);
            if (v[i].z <= thr) clist[warp][k++] = (unsigned short)(base + 2);
            if (v[i].w <= thr) clist[warp][k++] = (unsigned short)(base + 3);
        }
        __syncwarp();
        if (lane < total) {
            int code = clist[warp][lane];
            bd = exact_dist(zr, emb + ((size_t)code << 8), r2, g_e2[code]);
            bc = code;
        }
    } else {
        // Warp-parallel exact full scan (validated R13).
        #pragma unroll 1
        for (int s = 0; s < 32; ++s) {
            int code = (lane << 5) + s;
            float dist = exact_dist(zr, emb + ((size_t)code << 8),
                                    r2, g_e2[code]);
            if (dist < bd) { bd = dist; bc = code; }
        }
    }
    #pragma unroll
    for (int d = 16; d > 0; d >>= 1) {
        float od = __shfl_xor_sync(0xffffffffu, bd, d);
        int   oc = __shfl_xor_sync(0xffffffffu, bc, d);
        if (od < bd || (od == bd && oc < bc)) { bd = od; bc = oc; }
    }
    if (lane == 0) g_idx[tok] = bc;
}

// ===========================================================================
// Kernel 5: gather + straight-through output + loss partial sums (float4,
// measured 78us). out = fl(z + fl(q - z)); loss fl((q-z)^2) in double.
// ===========================================================================
__global__ void vq_output_kernel(const float* __restrict__ z,
                                 const float* __restrict__ emb,
                                 float* __restrict__ out) {
    double local = 0.0;
    const size_t nvec = NDATA >> 2;
    const size_t stride = (size_t)gridDim.x * blockDim.x;
    for (size_t i = (size_t)blockIdx.x * blockDim.x + threadIdx.x; i < nvec; i += stride) {
        size_t e = i << 2;
        int t  = (int)(e & 4095);
        int d  = (int)((e >> 12) & 255);
        int bb = (int)(e >> 20);
        int4 idx = *(const int4*)&g_idx[(bb << 12) + t];
        float4 zv = *(const float4*)&z[e];
        float q0 = __ldg(&emb[((size_t)idx.x << 8) + d]);
        float q1 = __ldg(&emb[((size_t)idx.y << 8) + d]);
        float q2 = __ldg(&emb[((size_t)idx.z << 8) + d]);
        float q3 = __ldg(&emb[((size_t)idx.w << 8) + d]);
        float d0 = __fsub_rn(q0, zv.x), d1 = __fsub_rn(q1, zv.y);
        float d2 = __fsub_rn(q2, zv.z), d3 = __fsub_rn(q3, zv.w);
        float4 ov = make_float4(__fadd_rn(zv.x, d0), __fadd_rn(zv.y, d1),
                                __fadd_rn(zv.z, d2), __fadd_rn(zv.w, d3));
        *(float4*)&out[e] = ov;
        local += (double)__fmul_rn(d0, d0) + (double)__fmul_rn(d1, d1)
               + (double)__fmul_rn(d2, d2) + (double)__fmul_rn(d3, d3);
    }
    #pragma unroll
    for (int off = 16; off > 0; off >>= 1)
        local += __shfl_down_sync(0xffffffffu, local, off);
    __shared__ double wsum[8];
    int lane = threadIdx.x & 31, wid = threadIdx.x >> 5;
    if (lane == 0) wsum[wid] = local;
    __syncthreads();
    if (threadIdx.x == 0) {
        double s = 0.0;
        #pragma unroll
        for (int i = 0; i < 8; ++i) s += wsum[i];
        atomicAdd(&g_loss_sum, s);
    }
}

// ===========================================================================
// Kernel 6: finalize loss = fl(m + fl(0.25*m)).
// ===========================================================================
__global__ void vq_finalize_kernel(float* __restrict__ out, int out_size) {
    if (threadIdx.x == 0 && blockIdx.x == 0) {
        if ((size_t)out_size > NDATA) {
            float m = (float)(g_loss_sum * (1.0 / 16777216.0));
            out[NDATA] = __fadd_rn(m, __fmul_rn(0.25f, m));
        }
    }
}

// ===========================================================================
extern "C" void kernel_launch(void* const* d_in, const int* in_sizes, int n_in,
                              void* d_out, int out_size) {
    const float* z   = (const float*)d_in[0];
    const float* emb = (const float*)d_in[1];
    if (n_in >= 2 && in_sizes[0] == KK * DD && (size_t)in_sizes[1] == NDATA) {
        const float* tmp = z; z = emb; emb = tmp;
    }
    float* out = (float*)d_out;

    cudaFuncSetAttribute((const void*)vq_mma_kernel,
                         cudaFuncAttributeMaxDynamicSharedMemorySize, SMEM_TOT);

    vq_prep_kernel<<<4, 256>>>(emb);
    vq_convert_kernel<<<dim3(TT / 32, DD / 32, BBATCH), dim3(32, 8)>>>(z);
    vq_r2_kernel<<<NTOK / 256, 256>>>();
    vq_mma_kernel<<<NTOK / 128, 512, SMEM_TOT>>>();
    vq_select_kernel<<<NTOK / 8, 256>>>(emb);
    vq_output_kernel<<<2048, 256>>>(z, emb, out);
    vq_finalize_kernel<<<1, 32>>>(out, out_size);
}

// round 15
// speedup vs baseline: 12.4327x; 1.0868x over previous
#include <cuda_runtime.h>
#include <cuda_fp16.h>
#include <math_constants.h>
#include <cstdint>

// Problem constants
#define DD 256
#define TT 4096
#define BBATCH 16
#define KK 1024
#define NTOK (BBATCH * TT)                  // 65536 tokens
#define NDATA ((size_t)BBATCH * DD * TT)    // 16777216 output data elements

// Scratch (no cudaMalloc allowed)
__device__ float          g_e2[KK];
__device__ float          g_r2[NTOK];
__device__ int            g_idx[NTOK];
__device__ double         g_loss_sum;
__device__ float          g_zt[NDATA];          // z transposed [token][d] fp32
__device__ __half         g_zh[NDATA];          // z transposed fp16
__device__ __half         g_eh[KK * DD];        // emb fp16
__device__ __half         g_dah[(size_t)NTOK * KK];  // approx dists fp16 (128 MB)

__device__ __forceinline__ uint32_t s2u(const void* p) {
    uint32_t a;
    asm("{ .reg .u64 t; cvta.to.shared.u64 t, %1; cvt.u32.u64 %0, t; }"
        : "=r"(a) : "l"(p));
    return a;
}

#define LDSM_X4(r0, r1, r2, r3, addr)                                          \
    asm volatile("ldmatrix.sync.aligned.m8n8.x4.shared.b16 {%0,%1,%2,%3}, [%4];" \
                 : "=r"(r0), "=r"(r1), "=r"(r2), "=r"(r3) : "r"(addr))

// fp16 HMMA (validated R14), u=2^-11.
#define MMA16816(d, a0, a1, a2, a3, b0, b1)                                    \
    asm volatile("mma.sync.aligned.m16n8k16.row.col.f32.f16.f16.f32 "          \
                 "{%0,%1,%2,%3}, {%4,%5,%6,%7}, {%8,%9}, {%0,%1,%2,%3};"       \
                 : "+f"((d)[0]), "+f"((d)[1]), "+f"((d)[2]), "+f"((d)[3])      \
                 : "r"(a0), "r"(a1), "r"(a2), "r"(a3), "r"(b0), "r"(b1))

#define CP_ASYNC16(dst, src)                                                   \
    asm volatile("cp.async.cg.shared.global [%0], [%1], 16;"                   \
                 :: "r"(dst), "l"(src))
#define CP_COMMIT() asm volatile("cp.async.commit_group;" ::: "memory")
#define CP_WAIT0()  asm volatile("cp.async.wait_group 0;" ::: "memory")

// Exact rescore of one code: sequential ascending-d fused fmaf (bit-matches
// the reference; validated R2/R7/R13/R14). float4 loads keep the fma order.
__device__ __forceinline__ float exact_dist(const float* __restrict__ zr,
                                            const float* __restrict__ er,
                                            float r2, float e2) {
    float acc = 0.0f;
    #pragma unroll 8
    for (int d = 0; d < DD; d += 4) {
        float4 z4 = *(const float4*)&zr[d];
        float4 e4 = __ldg((const float4*)&er[d]);
        acc = fmaf(z4.x, e4.x, acc);
        acc = fmaf(z4.y, e4.y, acc);
        acc = fmaf(z4.z, e4.z, acc);
        acc = fmaf(z4.w, e4.w, acc);
    }
    return __fsub_rn(__fadd_rn(r2, e2), __fmul_rn(2.0f, acc));
}

// ===========================================================================
// Kernel 0: exact ||e_k||^2 (sequential mul-then-add) + fp16 convert + zero loss
// ===========================================================================
__global__ void vq_prep_kernel(const float* __restrict__ emb) {
    int k = blockIdx.x * blockDim.x + threadIdx.x;
    if (k == 0) g_loss_sum = 0.0;
    if (k < KK) {
        const float* e = emb + (size_t)k * DD;
        float acc = 0.0f;
        #pragma unroll 8
        for (int d = 0; d < DD; ++d) {
            float v = e[d];
            acc = __fadd_rn(acc, __fmul_rn(v, v));
            g_eh[(size_t)k * DD + d] = __float2half_rn(v);
        }
        g_e2[k] = acc;
    }
}

// ===========================================================================
// Kernel 1: FUSED transpose (zt fp32 + zh fp16) + exact r2.
// R9-proven structure (rel_err 0.0 there; perf-exonerated by R12 A/B):
// CTA = 32 tokens x full 256 d, tile[256][33] = 33.8 KB static smem.
// Load [d][t] coalesced (128B rows); write-out float4-coalesced; r2 from the
// smem tile with the strictly-sequential ascending-d arithmetic (R2-exact).
// Saves the separate r2 kernel's 64 MB g_zt re-read.
// ===========================================================================
__global__ void __launch_bounds__(256) vq_convert_r2_kernel(const float* __restrict__ z) {
    __shared__ float tile[256][33];
    const int b = blockIdx.x >> 7, t0 = (blockIdx.x & 127) << 5;
    const int tid = threadIdx.x;
    const int tx = tid & 31, ty = tid >> 5;           // 32 x 8
    const float* src = z + (size_t)b * DD * TT + t0;
    #pragma unroll
    for (int k = 0; k < 32; ++k) {
        int d = ty + (k << 3);
        tile[d][tx] = src[(size_t)d * TT + tx];
    }
    __syncthreads();

    const int tok = tid >> 3, q = tid & 7;
    const size_t base = ((size_t)((b << 12) + t0 + tok)) * DD;
    #pragma unroll
    for (int jj = 0; jj < 8; ++jj) {
        int d0 = (jj << 5) + (q << 2);
        float4 v = make_float4(tile[d0][tok], tile[d0 + 1][tok],
                               tile[d0 + 2][tok], tile[d0 + 3][tok]);
        *(float4*)&g_zt[base + d0] = v;
        __half2 h01 = __floats2half2_rn(v.x, v.y);
        __half2 h23 = __floats2half2_rn(v.z, v.w);
        *(__half2*)&g_zh[base + d0]     = h01;
        *(__half2*)&g_zh[base + d0 + 2] = h23;
    }

    if (tid < 32) {
        float acc = 0.0f;
        #pragma unroll 8
        for (int d = 0; d < DD; ++d) {
            float v = tile[d][tid];
            acc = __fadd_rn(acc, __fmul_rn(v, v));
        }
        g_r2[(b << 12) + t0 + tid] = acc;
    }
}

// ===========================================================================
// Kernel 2: fp16 HMMA approx-dist GEMM (R14 winner, 147us measured).
// cp.async double-buffered B; fp16 epilogue.
// ===========================================================================
#define ES2_OFF 0                      // 4096 B
#define A_OFF   4096                   // 65536 B
#define B0_OFF  69632                  // 65536 B
#define B1_OFF  135168                 // 65536 B
#define SMEM_TOT 200704

__global__ void __launch_bounds__(512, 1) vq_mma_kernel() {
    extern __shared__ char smem[];
    const uint32_t sb = s2u(smem);
    const int tid = threadIdx.x, wid = tid >> 5, lane = tid & 31;
    const int tok0 = blockIdx.x << 7;
    float* es2s = (float*)(smem + ES2_OFF);

    es2s[tid]       = g_e2[tid];
    es2s[tid + 512] = g_e2[tid + 512];

    const uint4* zsrc = (const uint4*)(g_zh + ((size_t)tok0 << 8));
    #pragma unroll 2
    for (int i = tid; i < 4096; i += 512) {
        int row = i >> 5, kb = i & 31;
        CP_ASYNC16(sb + A_OFF + row * 512 + ((kb ^ (row & 7)) << 4), zsrc + i);
    }
    {
        const uint4* esrc = (const uint4*)g_eh;
        #pragma unroll 2
        for (int i = tid; i < 4096; i += 512) {
            int row = i >> 5, kb = i & 31;
            CP_ASYNC16(sb + B0_OFF + row * 512 + ((kb ^ (row & 7)) << 4), esrc + i);
        }
    }
    CP_COMMIT();
    CP_WAIT0();
    __syncthreads();

    const int rg = wid & 7, ch = wid >> 3;
    const int m0 = rg << 4, nb0 = ch << 6;
    const int lr = lane & 7;
    const int arow = m0 + lr + (((lane >> 3) & 1) << 3);
    const int akc  = lane >> 4;
    const int brow_off = lr + ((lane >> 4) << 3);
    const int bkc  = (lane >> 3) & 1;
    const uint32_t aBase = sb + A_OFF + (uint32_t)arow * 512;

    for (int c = 0; c < 8; ++c) {
        const int nc0 = c << 7;
        const uint32_t bOff = (c & 1) ? B1_OFF : B0_OFF;

        if (c < 7) {
            const uint32_t nOff = (c & 1) ? B0_OFF : B1_OFF;
            const uint4* esrc = (const uint4*)(g_eh + ((size_t)(nc0 + 128) << 8));
            #pragma unroll 2
            for (int i = tid; i < 4096; i += 512) {
                int row = i >> 5, kb = i & 31;
                CP_ASYNC16(sb + nOff + row * 512 + ((kb ^ (row & 7)) << 4), esrc + i);
            }
            CP_COMMIT();
        }

        float acc[8][4];
        #pragma unroll
        for (int nt = 0; nt < 8; ++nt)
            #pragma unroll
            for (int q = 0; q < 4; ++q) acc[nt][q] = 0.0f;

        #pragma unroll
        for (int s = 0; s < 16; ++s) {
            uint32_t a0, a1, a2, a3;
            int ach = 2 * s + akc;
            LDSM_X4(a0, a1, a2, a3, aBase + (uint32_t)((ach ^ (arow & 7)) << 4));
            #pragma unroll
            for (int p = 0; p < 4; ++p) {
                int brow = nb0 + (p << 4) + brow_off;
                int bch  = 2 * s + bkc;
                uint32_t b0, b1, b2, b3;
                LDSM_X4(b0, b1, b2, b3,
                        sb + bOff + (uint32_t)brow * 512
                                  + (uint32_t)((bch ^ (brow & 7)) << 4));
                MMA16816(acc[2 * p],     a0, a1, a2, a3, b0, b1);
                MMA16816(acc[2 * p + 1], a0, a1, a2, a3, b2, b3);
            }
        }

        {
            int r0 = tok0 + m0 + (lane >> 2);
            int cb = (lane & 3) << 1;
            #pragma unroll
            for (int nt = 0; nt < 8; ++nt) {
                int col = nb0 + (nt << 3) + cb;
                float e20 = es2s[nc0 + col];
                float e21 = es2s[nc0 + col + 1];
                __half2 v0 = __floats2half2_rn(fmaf(-2.0f, acc[nt][0], e20),
                                               fmaf(-2.0f, acc[nt][1], e21));
                __half2 v1 = __floats2half2_rn(fmaf(-2.0f, acc[nt][2], e20),
                                               fmaf(-2.0f, acc[nt][3], e21));
                *(__half2*)&g_dah[(size_t)r0 * KK + nc0 + col]       = v0;
                *(__half2*)&g_dah[(size_t)(r0 + 8) * KK + nc0 + col] = v1;
            }
        }

        if (c < 7) {
            CP_WAIT0();
            __syncthreads();
        }
    }
}

// ===========================================================================
// Kernel 3: warp-per-token select + exact rescore (R13/R14 winner).
// fp16-tight margin: dist_err <= 3.1e-5*||z||; margin = 8e-5*||z|| + 6e-4.
// Fallback >32 candidates: warp-parallel exact full scan.
// ===========================================================================
__global__ void __launch_bounds__(256) vq_select_kernel(const float* __restrict__ emb) {
    const int warp = threadIdx.x >> 5, lane = threadIdx.x & 31;
    const int tok = (blockIdx.x << 3) + warp;
    const __half* da = g_dah + (size_t)tok * KK;

    float4 v[8];
    float mn = CUDART_INF_F;
    #pragma unroll
    for (int i = 0; i < 8; ++i) {
        uint2 h = *(const uint2*)(da + (i << 7) + (lane << 2));
        float2 f01 = __half22float2(((const __half2*)&h)[0]);
        float2 f23 = __half22float2(((const __half2*)&h)[1]);
        v[i] = make_float4(f01.x, f01.y, f23.x, f23.y);
        mn = fminf(mn, fminf(fminf(v[i].x, v[i].y), fminf(v[i].z, v[i].w)));
    }
    #pragma unroll
    for (int off = 16; off > 0; off >>= 1)
        mn = fminf(mn, __shfl_xor_sync(0xffffffffu, mn, off));

    const float r2 = g_r2[tok];
    const float thr = mn + fmaf(8e-5f, sqrtf(r2), 6e-4f);

    int cnt = 0;
    #pragma unroll
    for (int i = 0; i < 8; ++i)
        cnt += (v[i].x <= thr) + (v[i].y <= thr) + (v[i].z <= thr) + (v[i].w <= thr);
    int off = cnt;
    #pragma unroll
    for (int d = 1; d < 32; d <<= 1) {
        int t2 = __shfl_up_sync(0xffffffffu, off, d);
        if (lane >= d) off += t2;
    }
    const int total = __shfl_sync(0xffffffffu, off, 31);
    const int excl = off - cnt;

    __shared__ unsigned short clist[8][36];
    const float* zr = g_zt + (size_t)tok * DD;

    float bd = CUDART_INF_F;
    int   bc = 0x7fffffff;

    if (total <= 32) {
        int k = excl;
        #pragma unroll
        for (int i = 0; i < 8; ++i) {
            int base = (i << 7) + (lane << 2);
            if (v[i].x <= thr) clist[warp][k++] = (unsigned short)(base + 0);
            if (v[i].y <= thr) clist[warp][k++] = (unsigned short)(base + 1);
            if (v[i].z <= thr) clist[warp][k++] = (unsigned short)(base + 2);
            if (v[i].w <= thr) clist[warp][k++] = (unsigned short)(base + 3);
        }
        __syncwarp();
        if (lane < total) {
            int code = clist[warp][lane];
            bd = exact_dist(zr, emb + ((size_t)code << 8), r2, g_e2[code]);
            bc = code;
        }
    } else {
        // Warp-parallel exact full scan (validated R13).
        #pragma unroll 1
        for (int s = 0; s < 32; ++s) {
            int code = (lane << 5) + s;
            float dist = exact_dist(zr, emb + ((size_t)code << 8),
                                    r2, g_e2[code]);
            if (dist < bd) { bd = dist; bc = code; }
        }
    }
    #pragma unroll
    for (int d = 16; d > 0; d >>= 1) {
        float od = __shfl_xor_sync(0xffffffffu, bd, d);
        int   oc = __shfl_xor_sync(0xffffffffu, bc, d);
        if (od < bd || (od == bd && oc < bc)) { bd = od; bc = oc; }
    }
    if (lane == 0) g_idx[tok] = bc;
}

// ===========================================================================
// Kernel 4: gather + straight-through output + loss partial sums (float4,
// measured 78us). out = fl(z + fl(q - z)); loss fl((q-z)^2) in double.
// ===========================================================================
__global__ void vq_output_kernel(const float* __restrict__ z,
                                 const float* __restrict__ emb,
                                 float* __restrict__ out) {
    double local = 0.0;
    const size_t nvec = NDATA >> 2;
    const size_t stride = (size_t)gridDim.x * blockDim.x;
    for (size_t i = (size_t)blockIdx.x * blockDim.x + threadIdx.x; i < nvec; i += stride) {
        size_t e = i << 2;
        int t  = (int)(e & 4095);
        int d  = (int)((e >> 12) & 255);
        int bb = (int)(e >> 20);
        int4 idx = *(const int4*)&g_idx[(bb << 12) + t];
        float4 zv = *(const float4*)&z[e];
        float q0 = __ldg(&emb[((size_t)idx.x << 8) + d]);
        float q1 = __ldg(&emb[((size_t)idx.y << 8) + d]);
        float q2 = __ldg(&emb[((size_t)idx.z << 8) + d]);
        float q3 = __ldg(&emb[((size_t)idx.w << 8) + d]);
        float d0 = __fsub_rn(q0, zv.x), d1 = __fsub_rn(q1, zv.y);
        float d2 = __fsub_rn(q2, zv.z), d3 = __fsub_rn(q3, zv.w);
        float4 ov = make_float4(__fadd_rn(zv.x, d0), __fadd_rn(zv.y, d1),
                                __fadd_rn(zv.z, d2), __fadd_rn(zv.w, d3));
        *(float4*)&out[e] = ov;
        local += (double)__fmul_rn(d0, d0) + (double)__fmul_rn(d1, d1)
               + (double)__fmul_rn(d2, d2) + (double)__fmul_rn(d3, d3);
    }
    #pragma unroll
    for (int off = 16; off > 0; off >>= 1)
        local += __shfl_down_sync(0xffffffffu, local, off);
    __shared__ double wsum[8];
    int lane = threadIdx.x & 31, wid = threadIdx.x >> 5;
    if (lane == 0) wsum[wid] = local;
    __syncthreads();
    if (threadIdx.x == 0) {
        double s = 0.0;
        #pragma unroll
        for (int i = 0; i < 8; ++i) s += wsum[i];
        atomicAdd(&g_loss_sum, s);
    }
}

// ===========================================================================
// Kernel 5: finalize loss = fl(m + fl(0.25*m)).
// ===========================================================================
__global__ void vq_finalize_kernel(float* __restrict__ out, int out_size) {
    if (threadIdx.x == 0 && blockIdx.x == 0) {
        if ((size_t)out_size > NDATA) {
            float m = (float)(g_loss_sum * (1.0 / 16777216.0));
            out[NDATA] = __fadd_rn(m, __fmul_rn(0.25f, m));
        }
    }
}

// ===========================================================================
extern "C" void kernel_launch(void* const* d_in, const int* in_sizes, int n_in,
                              void* d_out, int out_size) {
    const float* z   = (const float*)d_in[0];
    const float* emb = (const float*)d_in[1];
    if (n_in >= 2 && in_sizes[0] == KK * DD && (size_t)in_sizes[1] == NDATA) {
        const float* tmp = z; z = emb; emb = tmp;
    }
    float* out = (float*)d_out;

    cudaFuncSetAttribute((const void*)vq_mma_kernel,
                         cudaFuncAttributeMaxDynamicSharedMemorySize, SMEM_TOT);

    vq_prep_kernel<<<4, 256>>>(emb);
    vq_convert_r2_kernel<<<NTOK / 32, 256>>>(z);
    vq_mma_kernel<<<NTOK / 128, 512, SMEM_TOT>>>();
    vq_select_kernel<<<NTOK / 8, 256>>>(emb);
    vq_output_kernel<<<2048, 256>>>(z, emb, out);
    vq_finalize_kernel<<<1, 32>>>(out, out_size);
}